// round 15
// baseline (speedup 1.0000x reference)
#include <cuda_runtime.h>
#include <cuda_fp16.h>
#include <math.h>
#include <stdint.h>

#define T_TOK 4096
#define H_DIM 2048
#define I_DIM 1024
#define N_EXP 8

// ---------------- scratch (static device globals; no allocation) ------------
__device__ int   g_count[N_EXP];          // zero-init; re-zeroed by k_combine
__device__ int   g_tok [N_EXP * T_TOK];
__device__ float g_wt  [N_EXP * T_TOK];
__device__ int   g_slot[N_EXP * T_TOK];
__device__ float g_part[(size_t)T_TOK * 2 * H_DIM];   // 64 MB

// converted fp16 operands
__device__ __half cx_hi [(size_t)T_TOK * H_DIM];
__device__ __half cwg_hi[(size_t)N_EXP * I_DIM * H_DIM];
__device__ __half cwu_hi[(size_t)N_EXP * I_DIM * H_DIM];
__device__ __half cwd_hi[(size_t)N_EXP * H_DIM * I_DIM];
__device__ __half act_hi[(size_t)N_EXP * T_TOK * I_DIM];

// ======================= helpers ============================================
__device__ __forceinline__ uint32_t smem_u32(const void* p) {
    uint32_t a;
    asm("{ .reg .u64 t; cvta.to.shared.u64 t, %1; cvt.u32.u64 %0, t; }"
        : "=r"(a) : "l"(p));
    return a;
}

__device__ __forceinline__ void cp16(uint32_t s, const void* g) {
    asm volatile("cp.async.cg.shared.global [%0], [%1], 16;"
                 :: "r"(s), "l"(g) : "memory");
}
#define CP_COMMIT() asm volatile("cp.async.commit_group;" ::: "memory")
#define CP_WAIT(n)  asm volatile("cp.async.wait_group %0;" :: "n"(n) : "memory")

__device__ __forceinline__ void ldm4(uint32_t& r0, uint32_t& r1,
                                     uint32_t& r2, uint32_t& r3, uint32_t a) {
    asm volatile("ldmatrix.sync.aligned.m8n8.x4.shared.b16 {%0,%1,%2,%3}, [%4];"
                 : "=r"(r0), "=r"(r1), "=r"(r2), "=r"(r3) : "r"(a));
}

__device__ __forceinline__ void mma16816(float* c, const uint32_t* a,
                                         uint32_t b0, uint32_t b1) {
    asm volatile(
        "mma.sync.aligned.m16n8k16.row.col.f32.f16.f16.f32 "
        "{%0,%1,%2,%3}, {%4,%5,%6,%7}, {%8,%9}, {%0,%1,%2,%3};"
        : "+f"(c[0]), "+f"(c[1]), "+f"(c[2]), "+f"(c[3])
        : "r"(a[0]), "r"(a[1]), "r"(a[2]), "r"(a[3]), "r"(b0), "r"(b1));
}

__device__ __forceinline__ uint32_t pack2h(float a, float b) {
    __half2 hv = __floats2half2_rn(a, b);
    return *reinterpret_cast<uint32_t*>(&hv);
}

// streaming global access (evict-first) for the one-shot conversion stream
__device__ __forceinline__ float4 ldcs4(const float4* p) {
    float4 v;
    asm volatile("ld.global.cs.v4.f32 {%0,%1,%2,%3}, [%4];"
                 : "=f"(v.x), "=f"(v.y), "=f"(v.z), "=f"(v.w) : "l"(p));
    return v;
}
__device__ __forceinline__ void stcs4(uint4* p, uint4 v) {
    asm volatile("st.global.cs.v4.b32 [%0], {%1,%2,%3,%4};"
                 :: "l"(p), "r"(v.x), "r"(v.y), "r"(v.z), "r"(v.w) : "memory");
}

// ---------------- conversions: 16 floats/thread, MLP=4 front-batched --------
#define N4_W (N_EXP * I_DIM * H_DIM / 4)
#define NQ_W (N4_W / 4)   // quad-of-float4 index space per tensor

__device__ __forceinline__ void conv16(const float4* __restrict__ src,
                                       uint4* __restrict__ dst, int j) {
    float4 v0 = ldcs4(src + 4 * j);
    float4 v1 = ldcs4(src + 4 * j + 1);
    float4 v2 = ldcs4(src + 4 * j + 2);
    float4 v3 = ldcs4(src + 4 * j + 3);
    uint4 o0, o1;
    o0.x = pack2h(v0.x, v0.y); o0.y = pack2h(v0.z, v0.w);
    o0.z = pack2h(v1.x, v1.y); o0.w = pack2h(v1.z, v1.w);
    o1.x = pack2h(v2.x, v2.y); o1.y = pack2h(v2.z, v2.w);
    o1.z = pack2h(v3.x, v3.y); o1.w = pack2h(v3.z, v3.w);
    stcs4(dst + 2 * j, o0);
    stcs4(dst + 2 * j + 1, o1);
}

__global__ void k_conv_gu(const float4* __restrict__ wg, const float4* __restrict__ wu) {
    int i = blockIdx.x * 256 + threadIdx.x;
    if (i < NQ_W)             conv16(wg, (uint4*)cwg_hi, i);
    else if ((i -= NQ_W) < NQ_W) conv16(wu, (uint4*)cwu_hi, i);
}

__global__ void k_conv_d(const float4* __restrict__ wd) {
    int j = blockIdx.x * 256 + threadIdx.x;
    if (j < NQ_W) conv16(wd, (uint4*)cwd_hi, j);
}

// ---------------- router (fused x -> fp16 conversion, float2) ---------------
__global__ void k_router(const float2* __restrict__ x2,
                         const float* __restrict__ gw) {
    int gid  = blockIdx.x * blockDim.x + threadIdx.x;
    int t    = gid >> 5;
    int lane = gid & 31;
    if (t >= T_TOK) return;

    const float2* xr = x2 + (size_t)t * (H_DIM / 2);
    uint32_t* cxr = (uint32_t*)cx_hi + (size_t)t * (H_DIM / 2);

    float acc[N_EXP];
#pragma unroll
    for (int e = 0; e < N_EXP; e++) acc[e] = 0.f;

    for (int h2 = lane; h2 < H_DIM / 2; h2 += 32) {
        float2 xv = xr[h2];
        cxr[h2] = pack2h(xv.x, xv.y);          // fused fp16 conversion
#pragma unroll
        for (int e = 0; e < N_EXP; e++) {
            const float2 gv = *(const float2*)&gw[e * H_DIM + 2 * h2];
            acc[e] += xv.x * gv.x + xv.y * gv.y;
        }
    }
#pragma unroll
    for (int e = 0; e < N_EXP; e++) {
#pragma unroll
        for (int o = 16; o > 0; o >>= 1)
            acc[e] += __shfl_xor_sync(0xffffffffu, acc[e], o);
    }

    if (lane == 0) {
        float m = acc[0];
#pragma unroll
        for (int e = 1; e < N_EXP; e++) m = fmaxf(m, acc[e]);
        float p[N_EXP];
        float s = 0.f;
#pragma unroll
        for (int e = 0; e < N_EXP; e++) { p[e] = expf(acc[e] - m); s += p[e]; }
        float inv = 1.f / s;
#pragma unroll
        for (int e = 0; e < N_EXP; e++) p[e] *= inv;

        int e0 = 0;
#pragma unroll
        for (int e = 1; e < N_EXP; e++) if (p[e] > p[e0]) e0 = e;
        int e1 = -1;
#pragma unroll
        for (int e = 0; e < N_EXP; e++) {
            if (e == e0) continue;
            if (e1 < 0 || p[e] > p[e1]) e1 = e;
        }
        float den = p[e0] + p[e1];
        float w0 = p[e0] / den;
        float w1 = p[e1] / den;

        int pos0 = atomicAdd(&g_count[e0], 1);
        g_tok [e0 * T_TOK + pos0] = t;
        g_wt  [e0 * T_TOK + pos0] = w0;
        g_slot[e0 * T_TOK + pos0] = 0;

        int pos1 = atomicAdd(&g_count[e1], 1);
        g_tok [e1 * T_TOK + pos1] = t;
        g_wt  [e1 * T_TOK + pos1] = w1;
        g_slot[e1 * T_TOK + pos1] = 1;
    }
}

// ======================= GEMM1 (exact R8 structure) =========================
#define G1_PITCH 144
#define G1_STG   36864
#define G1_SMEM  (2 * G1_STG + 512)

__device__ __forceinline__ void g1_load(uint32_t sbase, int st, int kt,
                                        int e, int col0, const int* toks_s) {
    const int k0 = kt * 64;
    const uint32_t sb = sbase + st * G1_STG;
    const int tid = threadIdx.x;
#pragma unroll
    for (int j = 0; j < 8; j++) {             // A: 128 rows x 8 chunks of 16B
        int chunk = tid + j * 128;
        int row = chunk >> 3, c = chunk & 7;
        size_t go = (size_t)toks_s[row] * H_DIM + k0 + c * 8;
        cp16(sb + row * G1_PITCH + c * 16, cx_hi + go);
    }
#pragma unroll
    for (int j = 0; j < 4; j++) {             // Bg/Bu: 64 rows x 8 chunks each
        int chunk = tid + j * 128;
        int row = chunk >> 3, c = chunk & 7;
        size_t go = ((size_t)(e * I_DIM + col0 + row)) * H_DIM + k0 + c * 8;
        cp16(sb + 18432 + row * G1_PITCH + c * 16, cwg_hi + go);
        cp16(sb + 27648 + row * G1_PITCH + c * 16, cwu_hi + go);
    }
}

__global__ __launch_bounds__(128, 2) void k_gemm1() {
    extern __shared__ char smem[];
    const int e    = blockIdx.z;
    const int n    = g_count[e];
    const int row0 = blockIdx.x * 128;
    if (row0 >= n) return;
    const int col0 = blockIdx.y * 64;
    const int tid  = threadIdx.x;
    const int l    = tid & 31;
    const int w    = tid >> 5;
    const int m0   = (w & 1) * 64;
    const bool isU = (w >> 1);                // warps 2,3 = up

    int* toks_s = (int*)(smem + 2 * G1_STG);
    if (tid < 128) {
        int r = row0 + tid;
        toks_s[tid] = (r < n) ? g_tok[e * T_TOK + r] : 0;
    }
    __syncthreads();

    const uint32_t sbase = smem_u32(smem);

    float acc[4][8][4];
#pragma unroll
    for (int a = 0; a < 4; a++)
#pragma unroll
        for (int b = 0; b < 8; b++)
#pragma unroll
            for (int c = 0; c < 4; c++) acc[a][b][c] = 0.f;

    const int KT = H_DIM / 64;  // 32
    g1_load(sbase, 0, 0, e, col0, toks_s);
    CP_COMMIT();

    const uint32_t arow = (uint32_t)((l & 7) + ((l >> 3) & 1) * 8);
    const uint32_t brow = (uint32_t)((l & 7) + ((l >> 4) & 1) * 8);

    for (int kt = 0; kt < KT; kt++) {
        if (kt + 1 < KT) { g1_load(sbase, (kt + 1) & 1, kt + 1, e, col0, toks_s); CP_COMMIT(); }
        if (kt + 1 < KT) CP_WAIT(1); else CP_WAIT(0);
        __syncthreads();

        const uint32_t sA = sbase + (kt & 1) * G1_STG;
        const uint32_t sB = sA + (isU ? 27648 : 18432);

#pragma unroll
        for (int ks = 0; ks < 4; ks++) {
            const uint32_t acol = (uint32_t)(((l >> 4) * 8 + ks * 16) * 2);
            const uint32_t bcol = (uint32_t)((((l >> 3) & 1) * 8 + ks * 16) * 2);
            uint32_t ah[4][4];
#pragma unroll
            for (int mt = 0; mt < 4; mt++)
                ldm4(ah[mt][0], ah[mt][1], ah[mt][2], ah[mt][3],
                     sA + (m0 + mt * 16 + arow) * G1_PITCH + acol);
#pragma unroll
            for (int np = 0; np < 4; np++) {
                uint32_t bh[4];
                ldm4(bh[0], bh[1], bh[2], bh[3],
                     sB + (np * 16 + brow) * G1_PITCH + bcol);
#pragma unroll
                for (int mt = 0; mt < 4; mt++) {
                    mma16816(acc[mt][np * 2 + 0], ah[mt], bh[0], bh[1]);
                    mma16816(acc[mt][np * 2 + 1], ah[mt], bh[2], bh[3]);
                }
            }
        }
        __syncthreads();
    }

    // epilogue: up warps (2,3) -> smem, gate warps (0,1) compute silu(g)*u
    float* Ub = (float*)smem;   // 128 x 72 floats = 36864B = stage 0
    if (isU) {
#pragma unroll
        for (int mt = 0; mt < 4; mt++)
#pragma unroll
            for (int nt = 0; nt < 8; nt++) {
                int m  = m0 + mt * 16 + (l >> 2);
                int cc = nt * 8 + (l & 3) * 2;
                *(float2*)&Ub[m * 72 + cc]       = make_float2(acc[mt][nt][0], acc[mt][nt][1]);
                *(float2*)&Ub[(m + 8) * 72 + cc] = make_float2(acc[mt][nt][2], acc[mt][nt][3]);
            }
    }
    __syncthreads();
    if (!isU) {
#pragma unroll
        for (int mt = 0; mt < 4; mt++)
#pragma unroll
            for (int nt = 0; nt < 8; nt++) {
                int m  = m0 + mt * 16 + (l >> 2);
                int cc = nt * 8 + (l & 3) * 2;
#pragma unroll
                for (int half = 0; half < 2; half++) {
                    int mm = m + half * 8;
                    int rr = row0 + mm;
                    if (rr < n) {
                        float2 u = *(float2*)&Ub[mm * 72 + cc];
                        float g0 = acc[mt][nt][half * 2 + 0];
                        float g1 = acc[mt][nt][half * 2 + 1];
                        float a0 = g0 / (1.f + __expf(-g0)) * u.x;
                        float a1 = g1 / (1.f + __expf(-g1)) * u.y;
                        size_t idx = ((size_t)e * T_TOK + rr) * I_DIM + col0 + cc;
                        *(uint32_t*)(act_hi + idx) = pack2h(a0, a1);
                    }
                }
            }
    }
}

// ======================= GEMM2 (exact R8 structure) =========================
#define G2_PITCH 144
#define G2_STG   36864
#define G2_SMEM  (2 * G2_STG + 2048)

__device__ __forceinline__ void g2_load(uint32_t sbase, int st, int kt,
                                        int e, int row0, int col0) {
    const int k0 = kt * 64;
    const uint32_t sb = sbase + st * G2_STG;
    const int tid = threadIdx.x;
#pragma unroll
    for (int j = 0; j < 8; j++) {
        int chunk = tid + j * 128;
        int row = chunk >> 3, c = chunk & 7;
        size_t ga = ((size_t)e * T_TOK + row0 + row) * I_DIM + k0 + c * 8;
        cp16(sb + row * G2_PITCH + c * 16, act_hi + ga);
        size_t gb = ((size_t)(e * H_DIM + col0 + row)) * I_DIM + k0 + c * 8;
        cp16(sb + 18432 + row * G2_PITCH + c * 16, cwd_hi + gb);
    }
}

__global__ __launch_bounds__(128, 2) void k_gemm2() {
    extern __shared__ char smem[];
    const int e    = blockIdx.z;
    const int n    = g_count[e];
    const int row0 = blockIdx.x * 128;
    if (row0 >= n) return;
    const int col0 = blockIdx.y * 128;
    const int tid  = threadIdx.x;
    const int l    = tid & 31;
    const int w    = tid >> 5;
    const int m0   = (w & 1) * 64;
    const int nw0  = (w >> 1) * 64;

    int*   toks_s = (int*)  (smem + 2 * G2_STG);
    float* ws_s   = (float*)(smem + 2 * G2_STG + 512);
    int*   ks_s   = (int*)  (smem + 2 * G2_STG + 1024);
    if (tid < 128) {
        int r = row0 + tid;
        if (r < n) {
            toks_s[tid] = g_tok [e * T_TOK + r];
            ws_s[tid]   = g_wt  [e * T_TOK + r];
            ks_s[tid]   = g_slot[e * T_TOK + r];
        } else { toks_s[tid] = 0; ws_s[tid] = 0.f; ks_s[tid] = 0; }
    }
    __syncthreads();

    const uint32_t sbase = smem_u32(smem);

    float acc[4][8][4];
#pragma unroll
    for (int a = 0; a < 4; a++)
#pragma unroll
        for (int b = 0; b < 8; b++)
#pragma unroll
            for (int c = 0; c < 4; c++) acc[a][b][c] = 0.f;

    const int KT = I_DIM / 64;  // 16
    g2_load(sbase, 0, 0, e, row0, col0);
    CP_COMMIT();

    const uint32_t arow = (uint32_t)((l & 7) + ((l >> 3) & 1) * 8);
    const uint32_t brow = (uint32_t)((l & 7) + ((l >> 4) & 1) * 8);

    for (int kt = 0; kt < KT; kt++) {
        if (kt + 1 < KT) { g2_load(sbase, (kt + 1) & 1, kt + 1, e, row0, col0); CP_COMMIT(); }
        if (kt + 1 < KT) CP_WAIT(1); else CP_WAIT(0);
        __syncthreads();

        const uint32_t sA = sbase + (kt & 1) * G2_STG;
        const uint32_t sB = sA + 18432;

#pragma unroll
        for (int ks = 0; ks < 4; ks++) {
            const uint32_t acol = (uint32_t)(((l >> 4) * 8 + ks * 16) * 2);
            const uint32_t bcol = (uint32_t)((((l >> 3) & 1) * 8 + ks * 16) * 2);
            uint32_t ah[4][4];
#pragma unroll
            for (int mt = 0; mt < 4; mt++)
                ldm4(ah[mt][0], ah[mt][1], ah[mt][2], ah[mt][3],
                     sA + (m0 + mt * 16 + arow) * G2_PITCH + acol);
#pragma unroll
            for (int np = 0; np < 4; np++) {
                uint32_t bh[4];
                ldm4(bh[0], bh[1], bh[2], bh[3],
                     sB + (nw0 + np * 16 + brow) * G2_PITCH + bcol);
#pragma unroll
                for (int mt = 0; mt < 4; mt++) {
                    mma16816(acc[mt][np * 2 + 0], ah[mt], bh[0], bh[1]);
                    mma16816(acc[mt][np * 2 + 1], ah[mt], bh[2], bh[3]);
                }
            }
        }
        __syncthreads();
    }

    // epilogue: scale by routing weight, plain float2 stores into g_part
#pragma unroll
    for (int mt = 0; mt < 4; mt++)
#pragma unroll
        for (int nt = 0; nt < 8; nt++) {
            int m  = m0 + mt * 16 + (l >> 2);
            int cc = nw0 + nt * 8 + (l & 3) * 2;
#pragma unroll
            for (int half = 0; half < 2; half++) {
                int mm = m + half * 8;
                if (row0 + mm < n) {
                    int   t  = toks_s[mm];
                    int   k  = ks_s[mm];
                    float wt = ws_s[mm];
                    float2 v = make_float2(acc[mt][nt][half * 2 + 0] * wt,
                                           acc[mt][nt][half * 2 + 1] * wt);
                    *(float2*)&g_part[((size_t)t * 2 + k) * H_DIM + col0 + cc] = v;
                }
            }
        }
}

// ---------------- combine (+ reset g_count for next graph replay) -----------
__global__ void k_combine(float* __restrict__ out) {
    int i = blockIdx.x * 256 + threadIdx.x;
    if (blockIdx.x == 0 && threadIdx.x < N_EXP) g_count[threadIdx.x] = 0;
    if (i >= T_TOK * H_DIM) return;
    int t = i >> 11;
    int h = i & (H_DIM - 1);
    out[i] = g_part[((size_t)t * 2 + 0) * H_DIM + h] +
             g_part[((size_t)t * 2 + 1) * H_DIM + h];
}

// ---------------- launch: fork/join stream overlap ---------------------------
extern "C" void kernel_launch(void* const* d_in, const int* in_sizes, int n_in,
                              void* d_out, int out_size) {
    const float* x  = (const float*)d_in[0];
    const float* gw = (const float*)d_in[1];
    const float* wg = (const float*)d_in[2];
    const float* wu = (const float*)d_in[3];
    const float* wd = (const float*)d_in[4];
    float* out = (float*)d_out;

    static cudaStream_t sB = nullptr;
    static cudaEvent_t evFork, evXGU, evD;
    if (!sB) {
        cudaStreamCreateWithFlags(&sB, cudaStreamNonBlocking);
        cudaEventCreateWithFlags(&evFork, cudaEventDisableTiming);
        cudaEventCreateWithFlags(&evXGU, cudaEventDisableTiming);
        cudaEventCreateWithFlags(&evD,   cudaEventDisableTiming);
        cudaFuncSetAttribute(k_gemm1, cudaFuncAttributeMaxDynamicSharedMemorySize, G1_SMEM);
        cudaFuncSetAttribute(k_gemm2, cudaFuncAttributeMaxDynamicSharedMemorySize, G2_SMEM);
    }

    cudaEventRecord(evFork, 0);
    cudaStreamWaitEvent(sB, evFork, 0);

    // stream B: weight conversions (independent of router)
    k_conv_gu<<<(2 * NQ_W + 255) / 256, 256, 0, sB>>>(
        (const float4*)wg, (const float4*)wu);
    cudaEventRecord(evXGU, sB);
    k_conv_d<<<(NQ_W + 255) / 256, 256, 0, sB>>>((const float4*)wd);
    cudaEventRecord(evD, sB);

    // main stream: router (+ fused x conversion) overlaps conv_gu
    k_router<<<(T_TOK * 32) / 256, 256>>>((const float2*)x, gw);

    cudaStreamWaitEvent(0, evXGU, 0);   // gemm1 needs wg/wu conversions
    k_gemm1<<<dim3(T_TOK / 128, I_DIM / 64, N_EXP), 128, G1_SMEM>>>();

    cudaStreamWaitEvent(0, evD, 0);     // gemm2 needs wd conversion (overlapped gemm1)
    k_gemm2<<<dim3(T_TOK / 128, H_DIM / 128, N_EXP), 128, G2_SMEM>>>();
    k_combine<<<(T_TOK * H_DIM + 255) / 256, 256>>>(out);
}

// round 16
// speedup vs baseline: 1.0334x; 1.0334x over previous
#include <cuda_runtime.h>
#include <cuda_fp16.h>
#include <math.h>
#include <stdint.h>

#define T_TOK 4096
#define H_DIM 2048
#define I_DIM 1024
#define N_EXP 8

// ---------------- scratch (static device globals; no allocation) ------------
__device__ int    g_count[N_EXP];
__device__ int    g_tok [N_EXP * T_TOK];
__device__ float  g_wt  [N_EXP * T_TOK];
__device__ int    g_slot[N_EXP * T_TOK];
__device__ __half g_part[(size_t)T_TOK * 2 * H_DIM];   // fp16 partials (32 MB)

// converted fp16 operands
__device__ __half cx_hi [(size_t)T_TOK * H_DIM];
__device__ __half cwg_hi[(size_t)N_EXP * I_DIM * H_DIM];
__device__ __half cwu_hi[(size_t)N_EXP * I_DIM * H_DIM];
__device__ __half cwd_hi[(size_t)N_EXP * H_DIM * I_DIM];
__device__ __half act_hi[(size_t)N_EXP * T_TOK * I_DIM];

// ======================= helpers ============================================
__device__ __forceinline__ uint32_t smem_u32(const void* p) {
    uint32_t a;
    asm("{ .reg .u64 t; cvta.to.shared.u64 t, %1; cvt.u32.u64 %0, t; }"
        : "=r"(a) : "l"(p));
    return a;
}

__device__ __forceinline__ void cp16(uint32_t s, const void* g) {
    asm volatile("cp.async.cg.shared.global [%0], [%1], 16;"
                 :: "r"(s), "l"(g) : "memory");
}
#define CP_COMMIT() asm volatile("cp.async.commit_group;" ::: "memory")
#define CP_WAIT(n)  asm volatile("cp.async.wait_group %0;" :: "n"(n) : "memory")

__device__ __forceinline__ void ldm4(uint32_t& r0, uint32_t& r1,
                                     uint32_t& r2, uint32_t& r3, uint32_t a) {
    asm volatile("ldmatrix.sync.aligned.m8n8.x4.shared.b16 {%0,%1,%2,%3}, [%4];"
                 : "=r"(r0), "=r"(r1), "=r"(r2), "=r"(r3) : "r"(a));
}

__device__ __forceinline__ void mma16816(float* c, const uint32_t* a,
                                         uint32_t b0, uint32_t b1) {
    asm volatile(
        "mma.sync.aligned.m16n8k16.row.col.f32.f16.f16.f32 "
        "{%0,%1,%2,%3}, {%4,%5,%6,%7}, {%8,%9}, {%0,%1,%2,%3};"
        : "+f"(c[0]), "+f"(c[1]), "+f"(c[2]), "+f"(c[3])
        : "r"(a[0]), "r"(a[1]), "r"(a[2]), "r"(a[3]), "r"(b0), "r"(b1));
}

__device__ __forceinline__ uint32_t pack2h(float a, float b) {
    __half2 hv = __floats2half2_rn(a, b);
    return *reinterpret_cast<uint32_t*>(&hv);
}

// streaming global access (evict-first) for the one-shot conversion stream
__device__ __forceinline__ float4 ldcs4(const float4* p) {
    float4 v;
    asm volatile("ld.global.cs.v4.f32 {%0,%1,%2,%3}, [%4];"
                 : "=f"(v.x), "=f"(v.y), "=f"(v.z), "=f"(v.w) : "l"(p));
    return v;
}
__device__ __forceinline__ void stcs4(uint4* p, uint4 v) {
    asm volatile("st.global.cs.v4.b32 [%0], {%1,%2,%3,%4};"
                 :: "l"(p), "r"(v.x), "r"(v.y), "r"(v.z), "r"(v.w) : "memory");
}

// ---------------- init ------------------------------------------------------
__global__ void k_init() {
    if (threadIdx.x < N_EXP) g_count[threadIdx.x] = 0;
}

// ---------------- conversions (R13 forms) -----------------------------------
#define N4_W (N_EXP * I_DIM * H_DIM / 4)
#define NP_W (N4_W / 2)

__global__ void k_conv_gu(const float4* __restrict__ wg, const float4* __restrict__ wu) {
    int i = blockIdx.x * 256 + threadIdx.x;   // pair-of-float4 index
    const float4* src;
    uint4* dst;
    int j = i;
    if (i < NP_W)                { src = wg; dst = (uint4*)cwg_hi; }
    else if ((j -= NP_W) < NP_W) { src = wu; dst = (uint4*)cwu_hi; }
    else return;
    float4 v0 = ldcs4(src + 2 * j);
    float4 v1 = ldcs4(src + 2 * j + 1);
    uint4 o;
    o.x = pack2h(v0.x, v0.y); o.y = pack2h(v0.z, v0.w);
    o.z = pack2h(v1.x, v1.y); o.w = pack2h(v1.z, v1.w);
    stcs4(dst + j, o);
}

__global__ void k_conv_d(const float4* __restrict__ wd) {
    int j = blockIdx.x * 256 + threadIdx.x;
    if (j >= NP_W) return;
    float4 v0 = ldcs4(wd + 2 * j);
    float4 v1 = ldcs4(wd + 2 * j + 1);
    uint4 o;
    o.x = pack2h(v0.x, v0.y); o.y = pack2h(v0.z, v0.w);
    o.z = pack2h(v1.x, v1.y); o.w = pack2h(v1.z, v1.w);
    stcs4(((uint4*)cwd_hi) + j, o);
}

// ---------------- router (R13 form: fused x conversion, float2) -------------
__global__ void k_router(const float2* __restrict__ x2,
                         const float* __restrict__ gw) {
    int gid  = blockIdx.x * blockDim.x + threadIdx.x;
    int t    = gid >> 5;
    int lane = gid & 31;
    if (t >= T_TOK) return;

    const float2* xr = x2 + (size_t)t * (H_DIM / 2);
    uint32_t* cxr = (uint32_t*)cx_hi + (size_t)t * (H_DIM / 2);

    float acc[N_EXP];
#pragma unroll
    for (int e = 0; e < N_EXP; e++) acc[e] = 0.f;

    for (int h2 = lane; h2 < H_DIM / 2; h2 += 32) {
        float2 xv = xr[h2];
        cxr[h2] = pack2h(xv.x, xv.y);          // fused fp16 conversion
#pragma unroll
        for (int e = 0; e < N_EXP; e++) {
            const float2 gv = *(const float2*)&gw[e * H_DIM + 2 * h2];
            acc[e] += xv.x * gv.x + xv.y * gv.y;
        }
    }
#pragma unroll
    for (int e = 0; e < N_EXP; e++) {
#pragma unroll
        for (int o = 16; o > 0; o >>= 1)
            acc[e] += __shfl_xor_sync(0xffffffffu, acc[e], o);
    }

    if (lane == 0) {
        float m = acc[0];
#pragma unroll
        for (int e = 1; e < N_EXP; e++) m = fmaxf(m, acc[e]);
        float p[N_EXP];
        float s = 0.f;
#pragma unroll
        for (int e = 0; e < N_EXP; e++) { p[e] = expf(acc[e] - m); s += p[e]; }
        float inv = 1.f / s;
#pragma unroll
        for (int e = 0; e < N_EXP; e++) p[e] *= inv;

        int e0 = 0;
#pragma unroll
        for (int e = 1; e < N_EXP; e++) if (p[e] > p[e0]) e0 = e;
        int e1 = -1;
#pragma unroll
        for (int e = 0; e < N_EXP; e++) {
            if (e == e0) continue;
            if (e1 < 0 || p[e] > p[e1]) e1 = e;
        }
        float den = p[e0] + p[e1];
        float w0 = p[e0] / den;
        float w1 = p[e1] / den;

        int pos0 = atomicAdd(&g_count[e0], 1);
        g_tok [e0 * T_TOK + pos0] = t;
        g_wt  [e0 * T_TOK + pos0] = w0;
        g_slot[e0 * T_TOK + pos0] = 0;

        int pos1 = atomicAdd(&g_count[e1], 1);
        g_tok [e1 * T_TOK + pos1] = t;
        g_wt  [e1 * T_TOK + pos1] = w1;
        g_slot[e1 * T_TOK + pos1] = 1;
    }
}

// ======================= GEMM1 (exact R8 structure) =========================
#define G1_PITCH 144
#define G1_STG   36864
#define G1_SMEM  (2 * G1_STG + 512)

__device__ __forceinline__ void g1_load(uint32_t sbase, int st, int kt,
                                        int e, int col0, const int* toks_s) {
    const int k0 = kt * 64;
    const uint32_t sb = sbase + st * G1_STG;
    const int tid = threadIdx.x;
#pragma unroll
    for (int j = 0; j < 8; j++) {             // A: 128 rows x 8 chunks of 16B
        int chunk = tid + j * 128;
        int row = chunk >> 3, c = chunk & 7;
        size_t go = (size_t)toks_s[row] * H_DIM + k0 + c * 8;
        cp16(sb + row * G1_PITCH + c * 16, cx_hi + go);
    }
#pragma unroll
    for (int j = 0; j < 4; j++) {             // Bg/Bu: 64 rows x 8 chunks each
        int chunk = tid + j * 128;
        int row = chunk >> 3, c = chunk & 7;
        size_t go = ((size_t)(e * I_DIM + col0 + row)) * H_DIM + k0 + c * 8;
        cp16(sb + 18432 + row * G1_PITCH + c * 16, cwg_hi + go);
        cp16(sb + 27648 + row * G1_PITCH + c * 16, cwu_hi + go);
    }
}

__global__ __launch_bounds__(128, 2) void k_gemm1() {
    extern __shared__ char smem[];
    const int e    = blockIdx.z;
    const int n    = g_count[e];
    const int row0 = blockIdx.x * 128;
    if (row0 >= n) return;
    const int col0 = blockIdx.y * 64;
    const int tid  = threadIdx.x;
    const int l    = tid & 31;
    const int w    = tid >> 5;
    const int m0   = (w & 1) * 64;
    const bool isU = (w >> 1);                // warps 2,3 = up

    int* toks_s = (int*)(smem + 2 * G1_STG);
    if (tid < 128) {
        int r = row0 + tid;
        toks_s[tid] = (r < n) ? g_tok[e * T_TOK + r] : 0;
    }
    __syncthreads();

    const uint32_t sbase = smem_u32(smem);

    float acc[4][8][4];
#pragma unroll
    for (int a = 0; a < 4; a++)
#pragma unroll
        for (int b = 0; b < 8; b++)
#pragma unroll
            for (int c = 0; c < 4; c++) acc[a][b][c] = 0.f;

    const int KT = H_DIM / 64;  // 32
    g1_load(sbase, 0, 0, e, col0, toks_s);
    CP_COMMIT();

    const uint32_t arow = (uint32_t)((l & 7) + ((l >> 3) & 1) * 8);
    const uint32_t brow = (uint32_t)((l & 7) + ((l >> 4) & 1) * 8);

    for (int kt = 0; kt < KT; kt++) {
        if (kt + 1 < KT) { g1_load(sbase, (kt + 1) & 1, kt + 1, e, col0, toks_s); CP_COMMIT(); }
        if (kt + 1 < KT) CP_WAIT(1); else CP_WAIT(0);
        __syncthreads();

        const uint32_t sA = sbase + (kt & 1) * G1_STG;
        const uint32_t sB = sA + (isU ? 27648 : 18432);

#pragma unroll
        for (int ks = 0; ks < 4; ks++) {
            const uint32_t acol = (uint32_t)(((l >> 4) * 8 + ks * 16) * 2);
            const uint32_t bcol = (uint32_t)((((l >> 3) & 1) * 8 + ks * 16) * 2);
            uint32_t ah[4][4];
#pragma unroll
            for (int mt = 0; mt < 4; mt++)
                ldm4(ah[mt][0], ah[mt][1], ah[mt][2], ah[mt][3],
                     sA + (m0 + mt * 16 + arow) * G1_PITCH + acol);
#pragma unroll
            for (int np = 0; np < 4; np++) {
                uint32_t bh[4];
                ldm4(bh[0], bh[1], bh[2], bh[3],
                     sB + (np * 16 + brow) * G1_PITCH + bcol);
#pragma unroll
                for (int mt = 0; mt < 4; mt++) {
                    mma16816(acc[mt][np * 2 + 0], ah[mt], bh[0], bh[1]);
                    mma16816(acc[mt][np * 2 + 1], ah[mt], bh[2], bh[3]);
                }
            }
        }
        __syncthreads();
    }

    // epilogue: up warps (2,3) -> smem, gate warps (0,1) compute silu(g)*u
    float* Ub = (float*)smem;   // 128 x 72 floats = 36864B = stage 0
    if (isU) {
#pragma unroll
        for (int mt = 0; mt < 4; mt++)
#pragma unroll
            for (int nt = 0; nt < 8; nt++) {
                int m  = m0 + mt * 16 + (l >> 2);
                int cc = nt * 8 + (l & 3) * 2;
                *(float2*)&Ub[m * 72 + cc]       = make_float2(acc[mt][nt][0], acc[mt][nt][1]);
                *(float2*)&Ub[(m + 8) * 72 + cc] = make_float2(acc[mt][nt][2], acc[mt][nt][3]);
            }
    }
    __syncthreads();
    if (!isU) {
#pragma unroll
        for (int mt = 0; mt < 4; mt++)
#pragma unroll
            for (int nt = 0; nt < 8; nt++) {
                int m  = m0 + mt * 16 + (l >> 2);
                int cc = nt * 8 + (l & 3) * 2;
#pragma unroll
                for (int half = 0; half < 2; half++) {
                    int mm = m + half * 8;
                    int rr = row0 + mm;
                    if (rr < n) {
                        float2 u = *(float2*)&Ub[mm * 72 + cc];
                        float g0 = acc[mt][nt][half * 2 + 0];
                        float g1 = acc[mt][nt][half * 2 + 1];
                        float a0 = g0 / (1.f + __expf(-g0)) * u.x;
                        float a1 = g1 / (1.f + __expf(-g1)) * u.y;
                        size_t idx = ((size_t)e * T_TOK + rr) * I_DIM + col0 + cc;
                        *(uint32_t*)(act_hi + idx) = pack2h(a0, a1);
                    }
                }
            }
    }
}

// ======================= GEMM2 (R8 structure, fp16 partial stores) ==========
#define G2_PITCH 144
#define G2_STG   36864
#define G2_SMEM  (2 * G2_STG + 2048)

__device__ __forceinline__ void g2_load(uint32_t sbase, int st, int kt,
                                        int e, int row0, int col0) {
    const int k0 = kt * 64;
    const uint32_t sb = sbase + st * G2_STG;
    const int tid = threadIdx.x;
#pragma unroll
    for (int j = 0; j < 8; j++) {
        int chunk = tid + j * 128;
        int row = chunk >> 3, c = chunk & 7;
        size_t ga = ((size_t)e * T_TOK + row0 + row) * I_DIM + k0 + c * 8;
        cp16(sb + row * G2_PITCH + c * 16, act_hi + ga);
        size_t gb = ((size_t)(e * H_DIM + col0 + row)) * I_DIM + k0 + c * 8;
        cp16(sb + 18432 + row * G2_PITCH + c * 16, cwd_hi + gb);
    }
}

__global__ __launch_bounds__(128, 2) void k_gemm2() {
    extern __shared__ char smem[];
    const int e    = blockIdx.z;
    const int n    = g_count[e];
    const int row0 = blockIdx.x * 128;
    if (row0 >= n) return;
    const int col0 = blockIdx.y * 128;
    const int tid  = threadIdx.x;
    const int l    = tid & 31;
    const int w    = tid >> 5;
    const int m0   = (w & 1) * 64;
    const int nw0  = (w >> 1) * 64;

    int*   toks_s = (int*)  (smem + 2 * G2_STG);
    float* ws_s   = (float*)(smem + 2 * G2_STG + 512);
    int*   ks_s   = (int*)  (smem + 2 * G2_STG + 1024);
    if (tid < 128) {
        int r = row0 + tid;
        if (r < n) {
            toks_s[tid] = g_tok [e * T_TOK + r];
            ws_s[tid]   = g_wt  [e * T_TOK + r];
            ks_s[tid]   = g_slot[e * T_TOK + r];
        } else { toks_s[tid] = 0; ws_s[tid] = 0.f; ks_s[tid] = 0; }
    }
    __syncthreads();

    const uint32_t sbase = smem_u32(smem);

    float acc[4][8][4];
#pragma unroll
    for (int a = 0; a < 4; a++)
#pragma unroll
        for (int b = 0; b < 8; b++)
#pragma unroll
            for (int c = 0; c < 4; c++) acc[a][b][c] = 0.f;

    const int KT = I_DIM / 64;  // 16
    g2_load(sbase, 0, 0, e, row0, col0);
    CP_COMMIT();

    const uint32_t arow = (uint32_t)((l & 7) + ((l >> 3) & 1) * 8);
    const uint32_t brow = (uint32_t)((l & 7) + ((l >> 4) & 1) * 8);

    for (int kt = 0; kt < KT; kt++) {
        if (kt + 1 < KT) { g2_load(sbase, (kt + 1) & 1, kt + 1, e, row0, col0); CP_COMMIT(); }
        if (kt + 1 < KT) CP_WAIT(1); else CP_WAIT(0);
        __syncthreads();

        const uint32_t sA = sbase + (kt & 1) * G2_STG;
        const uint32_t sB = sA + 18432;

#pragma unroll
        for (int ks = 0; ks < 4; ks++) {
            const uint32_t acol = (uint32_t)(((l >> 4) * 8 + ks * 16) * 2);
            const uint32_t bcol = (uint32_t)((((l >> 3) & 1) * 8 + ks * 16) * 2);
            uint32_t ah[4][4];
#pragma unroll
            for (int mt = 0; mt < 4; mt++)
                ldm4(ah[mt][0], ah[mt][1], ah[mt][2], ah[mt][3],
                     sA + (m0 + mt * 16 + arow) * G2_PITCH + acol);
#pragma unroll
            for (int np = 0; np < 4; np++) {
                uint32_t bh[4];
                ldm4(bh[0], bh[1], bh[2], bh[3],
                     sB + (nw0 + np * 16 + brow) * G2_PITCH + bcol);
#pragma unroll
                for (int mt = 0; mt < 4; mt++) {
                    mma16816(acc[mt][np * 2 + 0], ah[mt], bh[0], bh[1]);
                    mma16816(acc[mt][np * 2 + 1], ah[mt], bh[2], bh[3]);
                }
            }
        }
        __syncthreads();
    }

    // epilogue: scale by routing weight, fp16 pair stores into g_part
#pragma unroll
    for (int mt = 0; mt < 4; mt++)
#pragma unroll
        for (int nt = 0; nt < 8; nt++) {
            int m  = m0 + mt * 16 + (l >> 2);
            int cc = nw0 + nt * 8 + (l & 3) * 2;
#pragma unroll
            for (int half = 0; half < 2; half++) {
                int mm = m + half * 8;
                if (row0 + mm < n) {
                    int   t  = toks_s[mm];
                    int   k  = ks_s[mm];
                    float wt = ws_s[mm];
                    uint32_t v = pack2h(acc[mt][nt][half * 2 + 0] * wt,
                                        acc[mt][nt][half * 2 + 1] * wt);
                    *(uint32_t*)&g_part[((size_t)t * 2 + k) * H_DIM + col0 + cc] = v;
                }
            }
        }
}

// ---------------- combine (fp16 partials -> fp32 out) -----------------------
__global__ void k_combine(float* __restrict__ out) {
    int i = blockIdx.x * 256 + threadIdx.x;          // half2-pair index
    if (i >= T_TOK * H_DIM / 2) return;
    int t  = i / (H_DIM / 2);
    int h2 = i - t * (H_DIM / 2);
    const uint32_t* gp = (const uint32_t*)g_part;
    __half2 a = *(const __half2*)&gp[((size_t)t * 2 + 0) * (H_DIM / 2) + h2];
    __half2 b = *(const __half2*)&gp[((size_t)t * 2 + 1) * (H_DIM / 2) + h2];
    float2 fa = __half22float2(a);
    float2 fb = __half22float2(b);
    *(float2*)&out[(size_t)t * H_DIM + 2 * h2] =
        make_float2(fa.x + fb.x, fa.y + fb.y);
}

// ---------------- launch: fork/join stream overlap (R13 topology) -----------
extern "C" void kernel_launch(void* const* d_in, const int* in_sizes, int n_in,
                              void* d_out, int out_size) {
    const float* x  = (const float*)d_in[0];
    const float* gw = (const float*)d_in[1];
    const float* wg = (const float*)d_in[2];
    const float* wu = (const float*)d_in[3];
    const float* wd = (const float*)d_in[4];
    float* out = (float*)d_out;

    static cudaStream_t sB = nullptr;
    static cudaEvent_t evFork, evXGU, evD;
    if (!sB) {
        cudaStreamCreateWithFlags(&sB, cudaStreamNonBlocking);
        cudaEventCreateWithFlags(&evFork, cudaEventDisableTiming);
        cudaEventCreateWithFlags(&evXGU, cudaEventDisableTiming);
        cudaEventCreateWithFlags(&evD,   cudaEventDisableTiming);
        cudaFuncSetAttribute(k_gemm1, cudaFuncAttributeMaxDynamicSharedMemorySize, G1_SMEM);
        cudaFuncSetAttribute(k_gemm2, cudaFuncAttributeMaxDynamicSharedMemorySize, G2_SMEM);
    }

    k_init<<<1, 32>>>();
    cudaEventRecord(evFork, 0);
    cudaStreamWaitEvent(sB, evFork, 0);

    // stream B: weight conversions (independent of router)
    k_conv_gu<<<(2 * NP_W + 255) / 256, 256, 0, sB>>>(
        (const float4*)wg, (const float4*)wu);
    cudaEventRecord(evXGU, sB);
    k_conv_d<<<(NP_W + 255) / 256, 256, 0, sB>>>((const float4*)wd);
    cudaEventRecord(evD, sB);

    // main stream: router (+ fused x conversion) overlaps conv_gu
    k_router<<<(T_TOK * 32) / 256, 256>>>((const float2*)x, gw);

    cudaStreamWaitEvent(0, evXGU, 0);   // gemm1 needs wg/wu conversions
    k_gemm1<<<dim3(T_TOK / 128, I_DIM / 64, N_EXP), 128, G1_SMEM>>>();

    cudaStreamWaitEvent(0, evD, 0);     // gemm2 needs wd conversion (overlapped gemm1)
    k_gemm2<<<dim3(T_TOK / 128, H_DIM / 128, N_EXP), 128, G2_SMEM>>>();
    k_combine<<<(T_TOK * H_DIM / 2 + 255) / 256, 256>>>(out);
}

// round 17
// speedup vs baseline: 1.0575x; 1.0234x over previous
#include <cuda_runtime.h>
#include <cuda_fp16.h>
#include <math.h>
#include <stdint.h>

#define T_TOK 4096
#define H_DIM 2048
#define I_DIM 1024
#define N_EXP 8

// ---------------- scratch (static device globals; no allocation) ------------
__device__ int    g_count[N_EXP];
__device__ int    g_tok [N_EXP * T_TOK];
__device__ float  g_wt  [N_EXP * T_TOK];
__device__ int    g_slot[N_EXP * T_TOK];
__device__ __half g_part[(size_t)T_TOK * 2 * H_DIM];   // fp16 partials (32 MB)

// converted fp16 operands
__device__ __half cx_hi [(size_t)T_TOK * H_DIM];
__device__ __half cwg_hi[(size_t)N_EXP * I_DIM * H_DIM];
__device__ __half cwu_hi[(size_t)N_EXP * I_DIM * H_DIM];
__device__ __half cwd_hi[(size_t)N_EXP * H_DIM * I_DIM];
__device__ __half act_hi[(size_t)N_EXP * T_TOK * I_DIM];

// ======================= helpers ============================================
__device__ __forceinline__ uint32_t smem_u32(const void* p) {
    uint32_t a;
    asm("{ .reg .u64 t; cvta.to.shared.u64 t, %1; cvt.u32.u64 %0, t; }"
        : "=r"(a) : "l"(p));
    return a;
}

__device__ __forceinline__ void cp16(uint32_t s, const void* g) {
    asm volatile("cp.async.cg.shared.global [%0], [%1], 16;"
                 :: "r"(s), "l"(g) : "memory");
}
#define CP_COMMIT() asm volatile("cp.async.commit_group;" ::: "memory")
#define CP_WAIT(n)  asm volatile("cp.async.wait_group %0;" :: "n"(n) : "memory")

__device__ __forceinline__ void ldm4(uint32_t& r0, uint32_t& r1,
                                     uint32_t& r2, uint32_t& r3, uint32_t a) {
    asm volatile("ldmatrix.sync.aligned.m8n8.x4.shared.b16 {%0,%1,%2,%3}, [%4];"
                 : "=r"(r0), "=r"(r1), "=r"(r2), "=r"(r3) : "r"(a));
}

__device__ __forceinline__ void mma16816(float* c, const uint32_t* a,
                                         uint32_t b0, uint32_t b1) {
    asm volatile(
        "mma.sync.aligned.m16n8k16.row.col.f32.f16.f16.f32 "
        "{%0,%1,%2,%3}, {%4,%5,%6,%7}, {%8,%9}, {%0,%1,%2,%3};"
        : "+f"(c[0]), "+f"(c[1]), "+f"(c[2]), "+f"(c[3])
        : "r"(a[0]), "r"(a[1]), "r"(a[2]), "r"(a[3]), "r"(b0), "r"(b1));
}

__device__ __forceinline__ uint32_t pack2h(float a, float b) {
    __half2 hv = __floats2half2_rn(a, b);
    return *reinterpret_cast<uint32_t*>(&hv);
}

// streaming global access (evict-first) for the one-shot conversion stream
__device__ __forceinline__ float4 ldcs4(const float4* p) {
    float4 v;
    asm volatile("ld.global.cs.v4.f32 {%0,%1,%2,%3}, [%4];"
                 : "=f"(v.x), "=f"(v.y), "=f"(v.z), "=f"(v.w) : "l"(p));
    return v;
}
__device__ __forceinline__ void stcs4(uint4* p, uint4 v) {
    asm volatile("st.global.cs.v4.b32 [%0], {%1,%2,%3,%4};"
                 :: "l"(p), "r"(v.x), "r"(v.y), "r"(v.z), "r"(v.w) : "memory");
}

// ---------------- init ------------------------------------------------------
__global__ void k_init() {
    if (threadIdx.x < N_EXP) g_count[threadIdx.x] = 0;
}

// ---------------- conversions (R13 forms) -----------------------------------
#define N4_W (N_EXP * I_DIM * H_DIM / 4)
#define NP_W (N4_W / 2)

__global__ void k_conv_gu(const float4* __restrict__ wg, const float4* __restrict__ wu) {
    int i = blockIdx.x * 256 + threadIdx.x;   // pair-of-float4 index
    const float4* src;
    uint4* dst;
    int j = i;
    if (i < NP_W)                { src = wg; dst = (uint4*)cwg_hi; }
    else if ((j -= NP_W) < NP_W) { src = wu; dst = (uint4*)cwu_hi; }
    else return;
    float4 v0 = ldcs4(src + 2 * j);
    float4 v1 = ldcs4(src + 2 * j + 1);
    uint4 o;
    o.x = pack2h(v0.x, v0.y); o.y = pack2h(v0.z, v0.w);
    o.z = pack2h(v1.x, v1.y); o.w = pack2h(v1.z, v1.w);
    stcs4(dst + j, o);
}

__global__ void k_conv_d(const float4* __restrict__ wd) {
    int j = blockIdx.x * 256 + threadIdx.x;
    if (j >= NP_W) return;
    float4 v0 = ldcs4(wd + 2 * j);
    float4 v1 = ldcs4(wd + 2 * j + 1);
    uint4 o;
    o.x = pack2h(v0.x, v0.y); o.y = pack2h(v0.z, v0.w);
    o.z = pack2h(v1.x, v1.y); o.w = pack2h(v1.z, v1.w);
    stcs4(((uint4*)cwd_hi) + j, o);
}

// ---------------- router (R13 form: fused x conversion, float2) -------------
__global__ void k_router(const float2* __restrict__ x2,
                         const float* __restrict__ gw) {
    int gid  = blockIdx.x * blockDim.x + threadIdx.x;
    int t    = gid >> 5;
    int lane = gid & 31;
    if (t >= T_TOK) return;

    const float2* xr = x2 + (size_t)t * (H_DIM / 2);
    uint32_t* cxr = (uint32_t*)cx_hi + (size_t)t * (H_DIM / 2);

    float acc[N_EXP];
#pragma unroll
    for (int e = 0; e < N_EXP; e++) acc[e] = 0.f;

    for (int h2 = lane; h2 < H_DIM / 2; h2 += 32) {
        float2 xv = xr[h2];
        cxr[h2] = pack2h(xv.x, xv.y);          // fused fp16 conversion
#pragma unroll
        for (int e = 0; e < N_EXP; e++) {
            const float2 gv = *(const float2*)&gw[e * H_DIM + 2 * h2];
            acc[e] += xv.x * gv.x + xv.y * gv.y;
        }
    }
#pragma unroll
    for (int e = 0; e < N_EXP; e++) {
#pragma unroll
        for (int o = 16; o > 0; o >>= 1)
            acc[e] += __shfl_xor_sync(0xffffffffu, acc[e], o);
    }

    if (lane == 0) {
        float m = acc[0];
#pragma unroll
        for (int e = 1; e < N_EXP; e++) m = fmaxf(m, acc[e]);
        float p[N_EXP];
        float s = 0.f;
#pragma unroll
        for (int e = 0; e < N_EXP; e++) { p[e] = expf(acc[e] - m); s += p[e]; }
        float inv = 1.f / s;
#pragma unroll
        for (int e = 0; e < N_EXP; e++) p[e] *= inv;

        int e0 = 0;
#pragma unroll
        for (int e = 1; e < N_EXP; e++) if (p[e] > p[e0]) e0 = e;
        int e1 = -1;
#pragma unroll
        for (int e = 0; e < N_EXP; e++) {
            if (e == e0) continue;
            if (e1 < 0 || p[e] > p[e1]) e1 = e;
        }
        float den = p[e0] + p[e1];
        float w0 = p[e0] / den;
        float w1 = p[e1] / den;

        int pos0 = atomicAdd(&g_count[e0], 1);
        g_tok [e0 * T_TOK + pos0] = t;
        g_wt  [e0 * T_TOK + pos0] = w0;
        g_slot[e0 * T_TOK + pos0] = 0;

        int pos1 = atomicAdd(&g_count[e1], 1);
        g_tok [e1 * T_TOK + pos1] = t;
        g_wt  [e1 * T_TOK + pos1] = w1;
        g_slot[e1 * T_TOK + pos1] = 1;
    }
}

// ======================= GEMM1 (exact R8 structure, expert-sliced) ==========
#define G1_PITCH 144
#define G1_STG   36864
#define G1_SMEM  (2 * G1_STG + 512)

__device__ __forceinline__ void g1_load(uint32_t sbase, int st, int kt,
                                        int e, int col0, const int* toks_s) {
    const int k0 = kt * 64;
    const uint32_t sb = sbase + st * G1_STG;
    const int tid = threadIdx.x;
#pragma unroll
    for (int j = 0; j < 8; j++) {             // A: 128 rows x 8 chunks of 16B
        int chunk = tid + j * 128;
        int row = chunk >> 3, c = chunk & 7;
        size_t go = (size_t)toks_s[row] * H_DIM + k0 + c * 8;
        cp16(sb + row * G1_PITCH + c * 16, cx_hi + go);
    }
#pragma unroll
    for (int j = 0; j < 4; j++) {             // Bg/Bu: 64 rows x 8 chunks each
        int chunk = tid + j * 128;
        int row = chunk >> 3, c = chunk & 7;
        size_t go = ((size_t)(e * I_DIM + col0 + row)) * H_DIM + k0 + c * 8;
        cp16(sb + 18432 + row * G1_PITCH + c * 16, cwg_hi + go);
        cp16(sb + 27648 + row * G1_PITCH + c * 16, cwu_hi + go);
    }
}

__global__ __launch_bounds__(128, 2) void k_gemm1(int ebase) {
    extern __shared__ char smem[];
    const int e    = ebase + blockIdx.z;
    const int n    = g_count[e];
    const int row0 = blockIdx.x * 128;
    if (row0 >= n) return;
    const int col0 = blockIdx.y * 64;
    const int tid  = threadIdx.x;
    const int l    = tid & 31;
    const int w    = tid >> 5;
    const int m0   = (w & 1) * 64;
    const bool isU = (w >> 1);                // warps 2,3 = up

    int* toks_s = (int*)(smem + 2 * G1_STG);
    if (tid < 128) {
        int r = row0 + tid;
        toks_s[tid] = (r < n) ? g_tok[e * T_TOK + r] : 0;
    }
    __syncthreads();

    const uint32_t sbase = smem_u32(smem);

    float acc[4][8][4];
#pragma unroll
    for (int a = 0; a < 4; a++)
#pragma unroll
        for (int b = 0; b < 8; b++)
#pragma unroll
            for (int c = 0; c < 4; c++) acc[a][b][c] = 0.f;

    const int KT = H_DIM / 64;  // 32
    g1_load(sbase, 0, 0, e, col0, toks_s);
    CP_COMMIT();

    const uint32_t arow = (uint32_t)((l & 7) + ((l >> 3) & 1) * 8);
    const uint32_t brow = (uint32_t)((l & 7) + ((l >> 4) & 1) * 8);

    for (int kt = 0; kt < KT; kt++) {
        if (kt + 1 < KT) { g1_load(sbase, (kt + 1) & 1, kt + 1, e, col0, toks_s); CP_COMMIT(); }
        if (kt + 1 < KT) CP_WAIT(1); else CP_WAIT(0);
        __syncthreads();

        const uint32_t sA = sbase + (kt & 1) * G1_STG;
        const uint32_t sB = sA + (isU ? 27648 : 18432);

#pragma unroll
        for (int ks = 0; ks < 4; ks++) {
            const uint32_t acol = (uint32_t)(((l >> 4) * 8 + ks * 16) * 2);
            const uint32_t bcol = (uint32_t)((((l >> 3) & 1) * 8 + ks * 16) * 2);
            uint32_t ah[4][4];
#pragma unroll
            for (int mt = 0; mt < 4; mt++)
                ldm4(ah[mt][0], ah[mt][1], ah[mt][2], ah[mt][3],
                     sA + (m0 + mt * 16 + arow) * G1_PITCH + acol);
#pragma unroll
            for (int np = 0; np < 4; np++) {
                uint32_t bh[4];
                ldm4(bh[0], bh[1], bh[2], bh[3],
                     sB + (np * 16 + brow) * G1_PITCH + bcol);
#pragma unroll
                for (int mt = 0; mt < 4; mt++) {
                    mma16816(acc[mt][np * 2 + 0], ah[mt], bh[0], bh[1]);
                    mma16816(acc[mt][np * 2 + 1], ah[mt], bh[2], bh[3]);
                }
            }
        }
        __syncthreads();
    }

    // epilogue: up warps (2,3) -> smem, gate warps (0,1) compute silu(g)*u
    float* Ub = (float*)smem;   // 128 x 72 floats = 36864B = stage 0
    if (isU) {
#pragma unroll
        for (int mt = 0; mt < 4; mt++)
#pragma unroll
            for (int nt = 0; nt < 8; nt++) {
                int m  = m0 + mt * 16 + (l >> 2);
                int cc = nt * 8 + (l & 3) * 2;
                *(float2*)&Ub[m * 72 + cc]       = make_float2(acc[mt][nt][0], acc[mt][nt][1]);
                *(float2*)&Ub[(m + 8) * 72 + cc] = make_float2(acc[mt][nt][2], acc[mt][nt][3]);
            }
    }
    __syncthreads();
    if (!isU) {
#pragma unroll
        for (int mt = 0; mt < 4; mt++)
#pragma unroll
            for (int nt = 0; nt < 8; nt++) {
                int m  = m0 + mt * 16 + (l >> 2);
                int cc = nt * 8 + (l & 3) * 2;
#pragma unroll
                for (int half = 0; half < 2; half++) {
                    int mm = m + half * 8;
                    int rr = row0 + mm;
                    if (rr < n) {
                        float2 u = *(float2*)&Ub[mm * 72 + cc];
                        float g0 = acc[mt][nt][half * 2 + 0];
                        float g1 = acc[mt][nt][half * 2 + 1];
                        float a0 = g0 / (1.f + __expf(-g0)) * u.x;
                        float a1 = g1 / (1.f + __expf(-g1)) * u.y;
                        size_t idx = ((size_t)e * T_TOK + rr) * I_DIM + col0 + cc;
                        *(uint32_t*)(act_hi + idx) = pack2h(a0, a1);
                    }
                }
            }
    }
}

// ======================= GEMM2 (R16 structure, expert-sliced) ===============
#define G2_PITCH 144
#define G2_STG   36864
#define G2_SMEM  (2 * G2_STG + 2048)

__device__ __forceinline__ void g2_load(uint32_t sbase, int st, int kt,
                                        int e, int row0, int col0) {
    const int k0 = kt * 64;
    const uint32_t sb = sbase + st * G2_STG;
    const int tid = threadIdx.x;
#pragma unroll
    for (int j = 0; j < 8; j++) {
        int chunk = tid + j * 128;
        int row = chunk >> 3, c = chunk & 7;
        size_t ga = ((size_t)e * T_TOK + row0 + row) * I_DIM + k0 + c * 8;
        cp16(sb + row * G2_PITCH + c * 16, act_hi + ga);
        size_t gb = ((size_t)(e * H_DIM + col0 + row)) * I_DIM + k0 + c * 8;
        cp16(sb + 18432 + row * G2_PITCH + c * 16, cwd_hi + gb);
    }
}

__global__ __launch_bounds__(128, 2) void k_gemm2(int ebase) {
    extern __shared__ char smem[];
    const int e    = ebase + blockIdx.z;
    const int n    = g_count[e];
    const int row0 = blockIdx.x * 128;
    if (row0 >= n) return;
    const int col0 = blockIdx.y * 128;
    const int tid  = threadIdx.x;
    const int l    = tid & 31;
    const int w    = tid >> 5;
    const int m0   = (w & 1) * 64;
    const int nw0  = (w >> 1) * 64;

    int*   toks_s = (int*)  (smem + 2 * G2_STG);
    float* ws_s   = (float*)(smem + 2 * G2_STG + 512);
    int*   ks_s   = (int*)  (smem + 2 * G2_STG + 1024);
    if (tid < 128) {
        int r = row0 + tid;
        if (r < n) {
            toks_s[tid] = g_tok [e * T_TOK + r];
            ws_s[tid]   = g_wt  [e * T_TOK + r];
            ks_s[tid]   = g_slot[e * T_TOK + r];
        } else { toks_s[tid] = 0; ws_s[tid] = 0.f; ks_s[tid] = 0; }
    }
    __syncthreads();

    const uint32_t sbase = smem_u32(smem);

    float acc[4][8][4];
#pragma unroll
    for (int a = 0; a < 4; a++)
#pragma unroll
        for (int b = 0; b < 8; b++)
#pragma unroll
            for (int c = 0; c < 4; c++) acc[a][b][c] = 0.f;

    const int KT = I_DIM / 64;  // 16
    g2_load(sbase, 0, 0, e, row0, col0);
    CP_COMMIT();

    const uint32_t arow = (uint32_t)((l & 7) + ((l >> 3) & 1) * 8);
    const uint32_t brow = (uint32_t)((l & 7) + ((l >> 4) & 1) * 8);

    for (int kt = 0; kt < KT; kt++) {
        if (kt + 1 < KT) { g2_load(sbase, (kt + 1) & 1, kt + 1, e, row0, col0); CP_COMMIT(); }
        if (kt + 1 < KT) CP_WAIT(1); else CP_WAIT(0);
        __syncthreads();

        const uint32_t sA = sbase + (kt & 1) * G2_STG;
        const uint32_t sB = sA + 18432;

#pragma unroll
        for (int ks = 0; ks < 4; ks++) {
            const uint32_t acol = (uint32_t)(((l >> 4) * 8 + ks * 16) * 2);
            const uint32_t bcol = (uint32_t)((((l >> 3) & 1) * 8 + ks * 16) * 2);
            uint32_t ah[4][4];
#pragma unroll
            for (int mt = 0; mt < 4; mt++)
                ldm4(ah[mt][0], ah[mt][1], ah[mt][2], ah[mt][3],
                     sA + (m0 + mt * 16 + arow) * G2_PITCH + acol);
#pragma unroll
            for (int np = 0; np < 4; np++) {
                uint32_t bh[4];
                ldm4(bh[0], bh[1], bh[2], bh[3],
                     sB + (nw0 + np * 16 + brow) * G2_PITCH + bcol);
#pragma unroll
                for (int mt = 0; mt < 4; mt++) {
                    mma16816(acc[mt][np * 2 + 0], ah[mt], bh[0], bh[1]);
                    mma16816(acc[mt][np * 2 + 1], ah[mt], bh[2], bh[3]);
                }
            }
        }
        __syncthreads();
    }

    // epilogue: scale by routing weight, fp16 pair stores into g_part
#pragma unroll
    for (int mt = 0; mt < 4; mt++)
#pragma unroll
        for (int nt = 0; nt < 8; nt++) {
            int m  = m0 + mt * 16 + (l >> 2);
            int cc = nw0 + nt * 8 + (l & 3) * 2;
#pragma unroll
            for (int half = 0; half < 2; half++) {
                int mm = m + half * 8;
                if (row0 + mm < n) {
                    int   t  = toks_s[mm];
                    int   k  = ks_s[mm];
                    float wt = ws_s[mm];
                    uint32_t v = pack2h(acc[mt][nt][half * 2 + 0] * wt,
                                        acc[mt][nt][half * 2 + 1] * wt);
                    *(uint32_t*)&g_part[((size_t)t * 2 + k) * H_DIM + col0 + cc] = v;
                }
            }
        }
}

// ---------------- combine (fp16 partials -> fp32 out) -----------------------
__global__ void k_combine(float* __restrict__ out) {
    int i = blockIdx.x * 256 + threadIdx.x;          // half2-pair index
    if (i >= T_TOK * H_DIM / 2) return;
    int t  = i / (H_DIM / 2);
    int h2 = i - t * (H_DIM / 2);
    const uint32_t* gp = (const uint32_t*)g_part;
    __half2 a = *(const __half2*)&gp[((size_t)t * 2 + 0) * (H_DIM / 2) + h2];
    __half2 b = *(const __half2*)&gp[((size_t)t * 2 + 1) * (H_DIM / 2) + h2];
    float2 fa = __half22float2(a);
    float2 fb = __half22float2(b);
    *(float2*)&out[(size_t)t * H_DIM + 2 * h2] =
        make_float2(fa.x + fb.x, fa.y + fb.y);
}

// ---------------- launch: expert-sliced fork/join overlap --------------------
extern "C" void kernel_launch(void* const* d_in, const int* in_sizes, int n_in,
                              void* d_out, int out_size) {
    const float* x  = (const float*)d_in[0];
    const float* gw = (const float*)d_in[1];
    const float* wg = (const float*)d_in[2];
    const float* wu = (const float*)d_in[3];
    const float* wd = (const float*)d_in[4];
    float* out = (float*)d_out;

    static cudaStream_t sB = nullptr;
    static cudaEvent_t evFork, evXGU, evD, evG1a, evG2a;
    if (!sB) {
        cudaStreamCreateWithFlags(&sB, cudaStreamNonBlocking);
        cudaEventCreateWithFlags(&evFork, cudaEventDisableTiming);
        cudaEventCreateWithFlags(&evXGU, cudaEventDisableTiming);
        cudaEventCreateWithFlags(&evD,   cudaEventDisableTiming);
        cudaEventCreateWithFlags(&evG1a, cudaEventDisableTiming);
        cudaEventCreateWithFlags(&evG2a, cudaEventDisableTiming);
        cudaFuncSetAttribute(k_gemm1, cudaFuncAttributeMaxDynamicSharedMemorySize, G1_SMEM);
        cudaFuncSetAttribute(k_gemm2, cudaFuncAttributeMaxDynamicSharedMemorySize, G2_SMEM);
    }

    k_init<<<1, 32>>>();
    cudaEventRecord(evFork, 0);
    cudaStreamWaitEvent(sB, evFork, 0);

    // stream B: weight conversions (independent of router)
    k_conv_gu<<<(2 * NP_W + 255) / 256, 256, 0, sB>>>(
        (const float4*)wg, (const float4*)wu);
    cudaEventRecord(evXGU, sB);
    k_conv_d<<<(NP_W + 255) / 256, 256, 0, sB>>>((const float4*)wd);
    cudaEventRecord(evD, sB);

    // main stream: router (+ fused x conversion) overlaps conv_gu
    k_router<<<(T_TOK * 32) / 256, 256>>>((const float2*)x, gw);

    cudaStreamWaitEvent(0, evXGU, 0);   // gemm1 needs wg/wu conversions
    k_gemm1<<<dim3(T_TOK / 128, I_DIM / 64, 4), 128, G1_SMEM>>>(0);   // E0-3
    cudaEventRecord(evG1a, 0);
    k_gemm1<<<dim3(T_TOK / 128, I_DIM / 64, 4), 128, G1_SMEM>>>(4);   // E4-7

    // stream B: gemm2 for E0-3 overlaps gemm1 E4-7 (after conv_d in sB order)
    cudaStreamWaitEvent(sB, evG1a, 0);
    k_gemm2<<<dim3(T_TOK / 128, H_DIM / 128, 4), 128, G2_SMEM, sB>>>(0);
    cudaEventRecord(evG2a, sB);

    // main: gemm2 for E4-7 (act ready same-stream; wd via evD)
    cudaStreamWaitEvent(0, evD, 0);
    k_gemm2<<<dim3(T_TOK / 128, H_DIM / 128, 4), 128, G2_SMEM>>>(4);

    cudaStreamWaitEvent(0, evG2a, 0);
    k_combine<<<(T_TOK * H_DIM / 2 + 255) / 256, 256>>>(out);
}